// round 1
// baseline (speedup 1.0000x reference)
#include <cuda_runtime.h>
#include <math.h>

#define D      256
#define NN     100000
#define EE     1000000
#define HALF_E (EE / 2)
#define RR     474
#define SCAN_BS 1024
#define NB_SCAN ((NN + SCAN_BS - 1) / SCAN_BS)   // 98
#define BN_EPS 1e-5f

// ---------------- static device scratch (no dynamic allocation) ----------------
__device__ float g_pre_in[(size_t)NN * D];   // 102.4 MB
__device__ float g_pre_out[(size_t)NN * D];  // 102.4 MB
__device__ int   g_cnt[NN];
__device__ int   g_start[NN];
__device__ int   g_cursor[NN];
__device__ int   g_eidx[EE];
__device__ float g_dinv[NN];
__device__ int   g_bsum[NB_SCAN];
__device__ float g_bias2[D];
__device__ float g_colsum[D];
__device__ float g_colsumsq[D];
__device__ float g_scale[D];
__device__ float g_shift[D];

// ---------------- kernels ----------------

// zero cnt + column stat accumulators
__global__ void k_zero() {
    int i = blockIdx.x * blockDim.x + threadIdx.x;
    if (i < NN) g_cnt[i] = 0;
    if (i < D) { g_colsum[i] = 0.f; g_colsumsq[i] = 0.f; }
}

// histogram of row indices (degree over all E edges)
__global__ void k_count(const int* __restrict__ rowp) {
    int e = blockIdx.x * blockDim.x + threadIdx.x;
    if (e < EE) atomicAdd(&g_cnt[rowp[e]], 1);
}

__global__ void k_dinv() {
    int i = blockIdx.x * blockDim.x + threadIdx.x;
    if (i < NN) {
        int c = g_cnt[i];
        g_dinv[i] = (c > 0) ? rsqrtf((float)c) : 0.f;
    }
}

// per-block inclusive scan (Hillis-Steele) -> exclusive scan chunk + block sums
__global__ void k_scan_local() {
    __shared__ int s[SCAN_BS];
    int t = threadIdx.x;
    int i = blockIdx.x * SCAN_BS + t;
    int v = (i < NN) ? g_cnt[i] : 0;
    s[t] = v;
    __syncthreads();
    for (int off = 1; off < SCAN_BS; off <<= 1) {
        int a = (t >= off) ? s[t - off] : 0;
        __syncthreads();
        s[t] += a;
        __syncthreads();
    }
    if (i < NN) g_start[i] = s[t] - v;  // exclusive within block
    if (t == SCAN_BS - 1) g_bsum[blockIdx.x] = s[t];
}

// sequential exclusive scan of block sums (98 elements, trivial)
__global__ void k_scan_bsum() {
    if (threadIdx.x == 0) {
        int acc = 0;
        for (int b = 0; b < NB_SCAN; b++) {
            int t = g_bsum[b];
            g_bsum[b] = acc;
            acc += t;
        }
    }
}

__global__ void k_scan_fixup() {
    int i = blockIdx.x * blockDim.x + threadIdx.x;
    if (i < NN) {
        int s = g_start[i] + g_bsum[i >> 10];
        g_start[i] = s;
        g_cursor[i] = s;
    }
}

// counting-sort fill: edge ids grouped by destination row
__global__ void k_fill(const int* __restrict__ rowp) {
    int e = blockIdx.x * blockDim.x + threadIdx.x;
    if (e < EE) {
        int pos = atomicAdd(&g_cursor[rowp[e]], 1);
        g_eidx[pos] = e;
    }
}

// one warp per node: accumulate norm*(x[col]-r[et]) into pre_in / pre_out
__global__ void k_aggregate(const float* __restrict__ x,
                            const float* __restrict__ r,
                            const int* __restrict__ colp,
                            const int* __restrict__ etp) {
    int node = blockIdx.x * 8 + (threadIdx.x >> 5);
    if (node >= NN) return;
    int lane = threadIdx.x & 31;
    int base = lane * 8;

    float4 ai0 = make_float4(0.f, 0.f, 0.f, 0.f), ai1 = ai0;
    float4 ao0 = ai0, ao1 = ai0;

    int s = g_start[node];
    int c = g_cnt[node];
    float di = g_dinv[node];

    for (int p = s; p < s + c; p++) {
        int e  = g_eidx[p];
        int cl = colp[e];
        int et = etp[e];
        float nrm = di * g_dinv[cl];
        const float4* xp = (const float4*)(x + (size_t)cl * D + base);
        const float4* rp = (const float4*)(r + (size_t)et * D + base);
        float4 xv0 = xp[0], xv1 = xp[1];
        float4 rv0 = rp[0], rv1 = rp[1];
        float4 d0 = make_float4(nrm * (xv0.x - rv0.x), nrm * (xv0.y - rv0.y),
                                nrm * (xv0.z - rv0.z), nrm * (xv0.w - rv0.w));
        float4 d1 = make_float4(nrm * (xv1.x - rv1.x), nrm * (xv1.y - rv1.y),
                                nrm * (xv1.z - rv1.z), nrm * (xv1.w - rv1.w));
        if (e < HALF_E) {
            ai0.x += d0.x; ai0.y += d0.y; ai0.z += d0.z; ai0.w += d0.w;
            ai1.x += d1.x; ai1.y += d1.y; ai1.z += d1.z; ai1.w += d1.w;
        } else {
            ao0.x += d0.x; ao0.y += d0.y; ao0.z += d0.z; ao0.w += d0.w;
            ao1.x += d1.x; ao1.y += d1.y; ao1.z += d1.z; ao1.w += d1.w;
        }
    }
    float4* pi = (float4*)(g_pre_in  + (size_t)node * D + base);
    float4* po = (float4*)(g_pre_out + (size_t)node * D + base);
    pi[0] = ai0; pi[1] = ai1;
    po[0] = ao0; po[1] = ao1;
}

// bias2 = bias - loop_rel @ w_loop
__global__ void k_bias2(const float* __restrict__ bias,
                        const float* __restrict__ loop_rel,
                        const float* __restrict__ w_loop) {
    int n = threadIdx.x;
    float acc = bias[n];
    for (int k = 0; k < D; k++)
        acc -= loop_rel[k] * w_loop[k * D + n];
    g_bias2[n] = acc;
}

// fused GEMM: h = pre_in@w_in + pre_out@w_out + x@w_loop + bias2
// block tile 128x128, BK=16, 256 threads, 8x8 per thread
__global__ void __launch_bounds__(256, 2)
k_gemm_h(const float* __restrict__ x,
         const float* __restrict__ w_in,
         const float* __restrict__ w_out,
         const float* __restrict__ w_loop,
         float* __restrict__ hout) {
    __shared__ float As[16][132];   // [k][row], padded
    __shared__ float Bs[16][128];   // [k][col]

    int tid = threadIdx.x;
    int tx = tid & 15, ty = tid >> 4;
    int rowBase = blockIdx.x * 128;
    int colBase = blockIdx.y * 128;

    float acc[8][8];
#pragma unroll
    for (int i = 0; i < 8; i++)
#pragma unroll
        for (int j = 0; j < 8; j++) acc[i][j] = 0.f;

    for (int src = 0; src < 3; src++) {
        const float* A = (src == 0) ? g_pre_in : (src == 1) ? g_pre_out : x;
        const float* B = (src == 0) ? w_in : (src == 1) ? w_out : w_loop;
        for (int kt = 0; kt < 16; kt++) {
            int kloc = kt * 16;
            // load A tile transposed: 512 float4, 2 per thread
#pragma unroll
            for (int i = 0; i < 2; i++) {
                int idx = tid + i * 256;   // float4 index
                int rrow = idx >> 2;       // 4 float4 per row of 16
                int kk4 = idx & 3;
                int grow = rowBase + rrow;
                float4 v = make_float4(0.f, 0.f, 0.f, 0.f);
                if (grow < NN)
                    v = *(const float4*)(A + (size_t)grow * D + kloc + kk4 * 4);
                As[kk4 * 4 + 0][rrow] = v.x;
                As[kk4 * 4 + 1][rrow] = v.y;
                As[kk4 * 4 + 2][rrow] = v.z;
                As[kk4 * 4 + 3][rrow] = v.w;
            }
            // load B tile: 16 x 128
#pragma unroll
            for (int i = 0; i < 2; i++) {
                int idx = tid + i * 256;   // float4 index, 32 per k-row
                int kk = idx >> 5;
                int c4 = idx & 31;
                float4 v = *(const float4*)(B + (size_t)(kloc + kk) * D + colBase + c4 * 4);
                *(float4*)&Bs[kk][c4 * 4] = v;
            }
            __syncthreads();
#pragma unroll
            for (int kk = 0; kk < 16; kk++) {
                float a[8], b[8];
                float4 a0 = *(const float4*)&As[kk][ty * 8];
                float4 a1 = *(const float4*)&As[kk][ty * 8 + 4];
                float4 b0 = *(const float4*)&Bs[kk][tx * 8];
                float4 b1 = *(const float4*)&Bs[kk][tx * 8 + 4];
                a[0]=a0.x; a[1]=a0.y; a[2]=a0.z; a[3]=a0.w;
                a[4]=a1.x; a[5]=a1.y; a[6]=a1.z; a[7]=a1.w;
                b[0]=b0.x; b[1]=b0.y; b[2]=b0.z; b[3]=b0.w;
                b[4]=b1.x; b[5]=b1.y; b[6]=b1.z; b[7]=b1.w;
#pragma unroll
                for (int i = 0; i < 8; i++)
#pragma unroll
                    for (int j = 0; j < 8; j++)
                        acc[i][j] += a[i] * b[j];
            }
            __syncthreads();
        }
    }
    // epilogue
#pragma unroll
    for (int i = 0; i < 8; i++) {
        int grow = rowBase + ty * 8 + i;
        if (grow >= NN) continue;
#pragma unroll
        for (int j = 0; j < 8; j += 4) {
            int gcol = colBase + tx * 8 + j;
            float4 o;
            o.x = acc[i][j + 0] + g_bias2[gcol + 0];
            o.y = acc[i][j + 1] + g_bias2[gcol + 1];
            o.z = acc[i][j + 2] + g_bias2[gcol + 2];
            o.w = acc[i][j + 3] + g_bias2[gcol + 3];
            *(float4*)(hout + (size_t)grow * D + gcol) = o;
        }
    }
}

// column sums / sums of squares over hout
__global__ void k_colstats(const float* __restrict__ hout) {
    int c = threadIdx.x;   // 256 threads = 256 columns
    float s = 0.f, s2 = 0.f;
    for (int row = blockIdx.x; row < NN; row += gridDim.x) {
        float v = hout[(size_t)row * D + c];
        s += v;
        s2 += v * v;
    }
    atomicAdd(&g_colsum[c], s);
    atomicAdd(&g_colsumsq[c], s2);
}

__global__ void k_bn_finalize(const float* __restrict__ gamma,
                              const float* __restrict__ beta) {
    int c = threadIdx.x;
    float mean = g_colsum[c] / (float)NN;
    float var = g_colsumsq[c] / (float)NN - mean * mean;
    float inv = rsqrtf(var + BN_EPS);
    float sc = gamma[c] * inv;
    g_scale[c] = sc;
    g_shift[c] = beta[c] - mean * sc;
}

__global__ void k_bn_apply(float* __restrict__ hout) {
    size_t i = (size_t)blockIdx.x * blockDim.x + threadIdx.x;
    size_t total = (size_t)NN * D;
    if (i < total) {
        int c = (int)(i & (D - 1));
        hout[i] = tanhf(hout[i] * g_scale[c] + g_shift[c]);
    }
}

// r_out = r @ w_rel  (474 x 256 x 256) — one block per row
__global__ void k_relgemm(const float* __restrict__ r,
                          const float* __restrict__ w_rel,
                          float* __restrict__ out) {
    int row = blockIdx.x;
    int n = threadIdx.x;
    const float* rr = r + (size_t)row * D;
    float acc = 0.f;
#pragma unroll 8
    for (int k = 0; k < D; k++)
        acc += rr[k] * w_rel[k * D + n];
    out[(size_t)row * D + n] = acc;
}

// ---------------- launch ----------------
extern "C" void kernel_launch(void* const* d_in, const int* in_sizes, int n_in,
                              void* d_out, int out_size) {
    const float* x        = (const float*)d_in[0];
    const float* r        = (const float*)d_in[1];
    const float* w_in     = (const float*)d_in[2];
    const float* w_out    = (const float*)d_in[3];
    const float* w_loop   = (const float*)d_in[4];
    const float* w_rel    = (const float*)d_in[5];
    const float* loop_rel = (const float*)d_in[6];
    const float* bias     = (const float*)d_in[7];
    const float* bn_gamma = (const float*)d_in[8];
    const float* bn_beta  = (const float*)d_in[9];
    const int*   edge_idx = (const int*)d_in[10];
    const int*   edge_typ = (const int*)d_in[11];

    const int* rowp = edge_idx;
    const int* colp = edge_idx + EE;

    float* hout = (float*)d_out;                      // [NN, D]
    float* rout = (float*)d_out + (size_t)NN * D;     // [RR, D]

    int gN = (NN + 255) / 256;
    int gE = (EE + 255) / 256;

    k_zero<<<gN, 256>>>();
    k_count<<<gE, 256>>>(rowp);
    k_dinv<<<gN, 256>>>();
    k_scan_local<<<NB_SCAN, SCAN_BS>>>();
    k_scan_bsum<<<1, 32>>>();
    k_scan_fixup<<<gN, 256>>>();
    k_fill<<<gE, 256>>>(rowp);
    k_aggregate<<<(NN + 7) / 8, 256>>>(x, r, colp, edge_typ);
    k_bias2<<<1, D>>>(bias, loop_rel, w_loop);

    dim3 gg((NN + 127) / 128, D / 128);
    k_gemm_h<<<gg, 256>>>(x, w_in, w_out, w_loop, hout);

    k_colstats<<<512, D>>>(hout);
    k_bn_finalize<<<1, D>>>(bn_gamma, bn_beta);
    k_bn_apply<<<(int)(((size_t)NN * D + 255) / 256), 256>>>(hout);

    k_relgemm<<<RR, D>>>(r, w_rel, rout);
}

// round 3
// speedup vs baseline: 1.4883x; 1.4883x over previous
#include <cuda_runtime.h>
#include <cuda_bf16.h>
#include <math.h>
#include <stdint.h>

#define D      256
#define NN     100000
#define EE     1000000
#define HALF_E (EE / 2)
#define RR     474
#define SCAN_BS 1024
#define NB_SCAN ((NN + SCAN_BS - 1) / SCAN_BS)   // 98
#define BN_EPS 1e-5f

#define KTOT   768          // combined K: [pre_in | pre_out | x]
#define NKS    48           // 768 / 16
#define GEMM_MBLK ((NN + 127) / 128)   // 782

// SMEM stage layout: A (2 splits x 128 rows x 48B) | B (2 x 128 x 48B)
#define ROWB    48
#define ASPL    (128 * ROWB)       // 6144
#define AREG    (2 * ASPL)         // 12288
#define STAGE   (2 * AREG)         // 24576
#define NSTAGE  3
#define SMEM_GEMM (NSTAGE * STAGE) // 73728

// ---------------- static device scratch ----------------
__device__ __nv_bfloat16 g_Ahi[(size_t)NN * KTOT];
__device__ __nv_bfloat16 g_Amid[(size_t)NN * KTOT];
__device__ __nv_bfloat16 g_Bhi[(size_t)D * KTOT];    // [n][k]
__device__ __nv_bfloat16 g_Bmid[(size_t)D * KTOT];
__device__ int      g_cnt[NN];
__device__ int      g_start[NN];
__device__ int      g_cursor[NN];
__device__ unsigned g_epack[EE];   // mode<<31 | et<<17 | col
__device__ float    g_dinv[NN];
__device__ int      g_bsum[NB_SCAN];
__device__ float    g_bias2[D];
__device__ float    g_colsum[D];
__device__ float    g_colsumsq[D];
__device__ float    g_scale[D];
__device__ float    g_shift[D];

// ---------------- helpers ----------------
__device__ __forceinline__ uint32_t smem_u32(const void* p) {
    uint32_t a;
    asm("{ .reg .u64 t; cvta.to.shared.u64 t, %1; cvt.u32.u64 %0, t; }" : "=r"(a) : "l"(p));
    return a;
}

#define CP_ASYNC16(dst, src, sz) \
    asm volatile("cp.async.cg.shared.global [%0], [%1], 16, %2;" \
        :: "r"(dst), "l"(src), "r"(sz) : "memory")
#define CP_COMMIT() asm volatile("cp.async.commit_group;" ::: "memory")
#define CP_WAIT2()  asm volatile("cp.async.wait_group 2;" ::: "memory")

#define LDMATRIX_X4(r0, r1, r2, r3, addr) \
    asm volatile("ldmatrix.sync.aligned.m8n8.x4.shared.b16 {%0,%1,%2,%3}, [%4];" \
        : "=r"(r0), "=r"(r1), "=r"(r2), "=r"(r3) : "r"(addr))

#define MMA16816(C, A, B0, B1) \
    asm volatile("mma.sync.aligned.m16n8k16.row.col.f32.bf16.bf16.f32 " \
        "{%0,%1,%2,%3}, {%4,%5,%6,%7}, {%8,%9}, {%0,%1,%2,%3};" \
        : "+f"((C)[0]), "+f"((C)[1]), "+f"((C)[2]), "+f"((C)[3]) \
        : "r"((A)[0]), "r"((A)[1]), "r"((A)[2]), "r"((A)[3]), "r"(B0), "r"(B1))

// split fp32 -> bf16 hi + bf16 mid, 8 values, 16B stores
__device__ __forceinline__ void split_store8(__nv_bfloat16* dHi, __nv_bfloat16* dMid,
                                             const float* v) {
    uint32_t h[4], m[4];
#pragma unroll
    for (int q = 0; q < 4; q++) {
        float a = v[2 * q], b = v[2 * q + 1];
        __nv_bfloat16 ha = __float2bfloat16_rn(a), hb = __float2bfloat16_rn(b);
        float ma = a - __bfloat162float(ha), mb = b - __bfloat162float(hb);
        __nv_bfloat162 hp; hp.x = ha; hp.y = hb;
        __nv_bfloat162 mp = __floats2bfloat162_rn(ma, mb);
        h[q] = *reinterpret_cast<uint32_t*>(&hp);
        m[q] = *reinterpret_cast<uint32_t*>(&mp);
    }
    *(uint4*)dHi = make_uint4(h[0], h[1], h[2], h[3]);
    *(uint4*)dMid = make_uint4(m[0], m[1], m[2], m[3]);
}

// ---------------- CSR build ----------------
__global__ void k_zero() {
    int i = blockIdx.x * blockDim.x + threadIdx.x;
    if (i < NN) g_cnt[i] = 0;
    if (i < D) { g_colsum[i] = 0.f; g_colsumsq[i] = 0.f; }
}
__global__ void k_count(const int* __restrict__ rowp) {
    int e = blockIdx.x * blockDim.x + threadIdx.x;
    if (e < EE) atomicAdd(&g_cnt[rowp[e]], 1);
}
__global__ void k_dinv() {
    int i = blockIdx.x * blockDim.x + threadIdx.x;
    if (i < NN) {
        int c = g_cnt[i];
        g_dinv[i] = (c > 0) ? rsqrtf((float)c) : 0.f;
    }
}
__global__ void k_scan_local() {
    __shared__ int s[SCAN_BS];
    int t = threadIdx.x;
    int i = blockIdx.x * SCAN_BS + t;
    int v = (i < NN) ? g_cnt[i] : 0;
    s[t] = v;
    __syncthreads();
    for (int off = 1; off < SCAN_BS; off <<= 1) {
        int a = (t >= off) ? s[t - off] : 0;
        __syncthreads();
        s[t] += a;
        __syncthreads();
    }
    if (i < NN) g_start[i] = s[t] - v;
    if (t == SCAN_BS - 1) g_bsum[blockIdx.x] = s[t];
}
__global__ void k_scan_bsum() {
    if (threadIdx.x == 0) {
        int acc = 0;
        for (int b = 0; b < NB_SCAN; b++) { int t = g_bsum[b]; g_bsum[b] = acc; acc += t; }
    }
}
__global__ void k_scan_fixup() {
    int i = blockIdx.x * blockDim.x + threadIdx.x;
    if (i < NN) {
        int s = g_start[i] + g_bsum[i >> 10];
        g_start[i] = s;
        g_cursor[i] = s;
    }
}
// counting-sort fill with packed payload: mode<<31 | et<<17 | col
__global__ void k_fill(const int* __restrict__ rowp,
                       const int* __restrict__ colp,
                       const int* __restrict__ etp) {
    int e = blockIdx.x * blockDim.x + threadIdx.x;
    if (e < EE) {
        int pos = atomicAdd(&g_cursor[rowp[e]], 1);
        unsigned pk = ((e < HALF_E) ? 0u : 0x80000000u) |
                      ((unsigned)etp[e] << 17) | (unsigned)colp[e];
        g_epack[pos] = pk;
    }
}

// ---------------- aggregate: bf16 hi/mid splits ----------------
__global__ void k_aggregate(const float* __restrict__ x,
                            const float* __restrict__ r) {
    int node = blockIdx.x * 8 + (threadIdx.x >> 5);
    if (node >= NN) return;
    int lane = threadIdx.x & 31;
    int base = lane * 8;

    float ain[8] = {0}, aout[8] = {0};
    int s = g_start[node];
    int c = g_cnt[node];
    float di = g_dinv[node];

    for (int p = s; p < s + c; p++) {
        unsigned pk = g_epack[p];
        int cl = pk & 0x1FFFF;
        int et = (pk >> 17) & 0x1FF;
        float nrm = di * g_dinv[cl];
        const float4* xp = (const float4*)(x + (size_t)cl * D + base);
        const float4* rp = (const float4*)(r + (size_t)et * D + base);
        float4 xv0 = xp[0], xv1 = xp[1];
        float4 rv0 = rp[0], rv1 = rp[1];
        float d0[8] = {xv0.x - rv0.x, xv0.y - rv0.y, xv0.z - rv0.z, xv0.w - rv0.w,
                       xv1.x - rv1.x, xv1.y - rv1.y, xv1.z - rv1.z, xv1.w - rv1.w};
        if (!(pk & 0x80000000u)) {
#pragma unroll
            for (int j = 0; j < 8; j++) ain[j] += nrm * d0[j];
        } else {
#pragma unroll
            for (int j = 0; j < 8; j++) aout[j] += nrm * d0[j];
        }
    }
    size_t rb = (size_t)node * KTOT;
    split_store8(g_Ahi + rb + base,       g_Amid + rb + base,       ain);
    split_store8(g_Ahi + rb + 256 + base, g_Amid + rb + 256 + base, aout);
}

// x -> A columns [512, 768)
__global__ void k_xsplit(const float* __restrict__ x) {
    int gid = blockIdx.x * blockDim.x + threadIdx.x;
    if (gid >= NN * 32) return;
    int row = gid >> 5, c8 = gid & 31;
    const float4* src = (const float4*)(x + (size_t)row * D + c8 * 8);
    float4 v0 = src[0], v1 = src[1];
    float v[8] = {v0.x, v0.y, v0.z, v0.w, v1.x, v1.y, v1.z, v1.w};
    size_t off = (size_t)row * KTOT + 512 + c8 * 8;
    split_store8(g_Ahi + off, g_Amid + off, v);
}

// W -> transposed split B [n][k]
__global__ void k_bsplit(const float* __restrict__ w_in,
                         const float* __restrict__ w_out,
                         const float* __restrict__ w_loop) {
    int k = blockIdx.x;
    int n = threadIdx.x;
    const float* W = (k < 256) ? w_in : (k < 512) ? w_out : w_loop;
    float v = W[(size_t)(k & 255) * D + n];
    __nv_bfloat16 h = __float2bfloat16_rn(v);
    g_Bhi[(size_t)n * KTOT + k] = h;
    g_Bmid[(size_t)n * KTOT + k] = __float2bfloat16_rn(v - __bfloat162float(h));
}

__global__ void k_bias2(const float* __restrict__ bias,
                        const float* __restrict__ loop_rel,
                        const float* __restrict__ w_loop) {
    int n = threadIdx.x;
    float acc = bias[n];
    for (int k = 0; k < D; k++)
        acc -= loop_rel[k] * w_loop[k * D + n];
    g_bias2[n] = acc;
}

// ---------------- mma.sync bf16x3 GEMM ----------------
__device__ __forceinline__ void load_stage(uint32_t sb, int buf, int kOff,
                                           int rowBase, int colBase, int tid) {
    uint32_t base = sb + buf * STAGE;
#pragma unroll
    for (int i = 0; i < 4; i++) {
        int c = tid + i * 256;
        int isB   = c >> 9;
        int split = (c >> 8) & 1;
        int row   = (c >> 1) & 127;
        int half  = c & 1;
        uint32_t dst = base + isB * AREG + split * ASPL + row * ROWB + half * 16;
        const __nv_bfloat16* src;
        int sz = 16;
        if (!isB) {
            int gr = rowBase + row;
            if (gr >= NN) { gr = 0; sz = 0; }
            src = (split ? g_Amid : g_Ahi) + (size_t)gr * KTOT + kOff + half * 8;
        } else {
            int gc = colBase + row;
            src = (split ? g_Bmid : g_Bhi) + (size_t)gc * KTOT + kOff + half * 8;
        }
        CP_ASYNC16(dst, (const void*)src, sz);
    }
}

__global__ void __launch_bounds__(256, 1)
k_gemm_mma(float* __restrict__ hout) {
    extern __shared__ char smem[];
    uint32_t sb = smem_u32(smem);
    int tid = threadIdx.x;
    int lane = tid & 31, wid = tid >> 5;
    int warp_m = wid & 1;        // 2 warps over M=128 (m64 each)
    int warp_n = wid >> 1;       // 4 warps over N=128 (n32 each)
    int rowBase = blockIdx.x * 128;
    int colBase = blockIdx.y * 128;

    float c[4][4][4];
#pragma unroll
    for (int i = 0; i < 4; i++)
#pragma unroll
        for (int j = 0; j < 4; j++)
#pragma unroll
            for (int q = 0; q < 4; q++) c[i][j][q] = 0.f;

    // prologue: stages 0..2
#pragma unroll
    for (int s = 0; s < NSTAGE; s++) {
        load_stage(sb, s, s * 16, rowBase, colBase, tid);
        CP_COMMIT();
    }

    uint32_t a_off = (lane & 15) * ROWB + (lane >> 4) * 16;
    uint32_t b_off = (((lane >> 4) << 3) + (lane & 7)) * ROWB + ((lane >> 3) & 1) * 16;

    for (int ks = 0; ks < NKS; ks++) {
        CP_WAIT2();
        __syncthreads();
        uint32_t st = sb + (ks % 3) * STAGE;

        uint32_t a[2][4][4];
#pragma unroll
        for (int split = 0; split < 2; split++)
#pragma unroll
            for (int mt = 0; mt < 4; mt++) {
                uint32_t addr = st + split * ASPL +
                                (warp_m * 64 + mt * 16) * ROWB + a_off;
                LDMATRIX_X4(a[split][mt][0], a[split][mt][1],
                            a[split][mt][2], a[split][mt][3], addr);
            }
        uint32_t b[2][2][4];
#pragma unroll
        for (int split = 0; split < 2; split++)
#pragma unroll
            for (int pr = 0; pr < 2; pr++) {
                uint32_t addr = st + AREG + split * ASPL +
                                (warp_n * 32 + pr * 16) * ROWB + b_off;
                LDMATRIX_X4(b[split][pr][0], b[split][pr][1],
                            b[split][pr][2], b[split][pr][3], addr);
            }
#pragma unroll
        for (int mt = 0; mt < 4; mt++)
#pragma unroll
            for (int nt = 0; nt < 4; nt++) {
                int pr = nt >> 1, ix = (nt & 1) * 2;
                MMA16816(c[mt][nt], a[0][mt], b[0][pr][ix], b[0][pr][ix + 1]);
                MMA16816(c[mt][nt], a[0][mt], b[1][pr][ix], b[1][pr][ix + 1]);
                MMA16816(c[mt][nt], a[1][mt], b[0][pr][ix], b[0][pr][ix + 1]);
            }
        __syncthreads();
        if (ks + 3 < NKS)
            load_stage(sb, ks % 3, (ks + 3) * 16, rowBase, colBase, tid);
        CP_COMMIT();
    }

    // epilogue
#pragma unroll
    for (int nt = 0; nt < 4; nt++) {
        int col = colBase + warp_n * 32 + nt * 8 + (lane & 3) * 2;
        float b0 = g_bias2[col], b1 = g_bias2[col + 1];
#pragma unroll
        for (int mt = 0; mt < 4; mt++) {
            int row = rowBase + warp_m * 64 + mt * 16 + (lane >> 2);
            if (row < NN) {
                float2 o = make_float2(c[mt][nt][0] + b0, c[mt][nt][1] + b1);
                *(float2*)(hout + (size_t)row * D + col) = o;
            }
            int row2 = row + 8;
            if (row2 < NN) {
                float2 o = make_float2(c[mt][nt][2] + b0, c[mt][nt][3] + b1);
                *(float2*)(hout + (size_t)row2 * D + col) = o;
            }
        }
    }
}

// ---------------- BN + tanh + rel GEMM ----------------
__global__ void k_colstats(const float* __restrict__ hout) {
    int c = threadIdx.x;
    float s = 0.f, s2 = 0.f;
    for (int row = blockIdx.x; row < NN; row += gridDim.x) {
        float v = hout[(size_t)row * D + c];
        s += v;
        s2 += v * v;
    }
    atomicAdd(&g_colsum[c], s);
    atomicAdd(&g_colsumsq[c], s2);
}
__global__ void k_bn_finalize(const float* __restrict__ gamma,
                              const float* __restrict__ beta) {
    int c = threadIdx.x;
    float mean = g_colsum[c] / (float)NN;
    float var = g_colsumsq[c] / (float)NN - mean * mean;
    float inv = rsqrtf(var + BN_EPS);
    float sc = gamma[c] * inv;
    g_scale[c] = sc;
    g_shift[c] = beta[c] - mean * sc;
}
__global__ void k_bn_apply(float* __restrict__ hout) {
    size_t i = (size_t)blockIdx.x * blockDim.x + threadIdx.x;
    size_t total = (size_t)NN * D;
    if (i < total) {
        int c = (int)(i & (D - 1));
        hout[i] = tanhf(hout[i] * g_scale[c] + g_shift[c]);
    }
}
__global__ void k_relgemm(const float* __restrict__ r,
                          const float* __restrict__ w_rel,
                          float* __restrict__ out) {
    int row = blockIdx.x;
    int n = threadIdx.x;
    const float* rr = r + (size_t)row * D;
    float acc = 0.f;
#pragma unroll 8
    for (int k = 0; k < D; k++)
        acc += rr[k] * w_rel[k * D + n];
    out[(size_t)row * D + n] = acc;
}

// ---------------- launch ----------------
extern "C" void kernel_launch(void* const* d_in, const int* in_sizes, int n_in,
                              void* d_out, int out_size) {
    const float* x        = (const float*)d_in[0];
    const float* r        = (const float*)d_in[1];
    const float* w_in     = (const float*)d_in[2];
    const float* w_out    = (const float*)d_in[3];
    const float* w_loop   = (const float*)d_in[4];
    const float* w_rel    = (const float*)d_in[5];
    const float* loop_rel = (const float*)d_in[6];
    const float* bias     = (const float*)d_in[7];
    const float* bn_gamma = (const float*)d_in[8];
    const float* bn_beta  = (const float*)d_in[9];
    const int*   edge_idx = (const int*)d_in[10];
    const int*   edge_typ = (const int*)d_in[11];

    const int* rowp = edge_idx;
    const int* colp = edge_idx + EE;

    float* hout = (float*)d_out;
    float* rout = (float*)d_out + (size_t)NN * D;

    int gN = (NN + 255) / 256;
    int gE = (EE + 255) / 256;

    cudaFuncSetAttribute(k_gemm_mma, cudaFuncAttributeMaxDynamicSharedMemorySize, SMEM_GEMM);

    k_zero<<<gN, 256>>>();
    k_count<<<gE, 256>>>(rowp);
    k_dinv<<<gN, 256>>>();
    k_scan_local<<<NB_SCAN, SCAN_BS>>>();
    k_scan_bsum<<<1, 32>>>();
    k_scan_fixup<<<gN, 256>>>();
    k_fill<<<gE, 256>>>(rowp, colp, edge_typ);
    k_aggregate<<<(NN + 7) / 8, 256>>>(x, r);
    k_xsplit<<<(NN * 32 + 255) / 256, 256>>>(x);
    k_bsplit<<<KTOT, D>>>(w_in, w_out, w_loop);
    k_bias2<<<1, D>>>(bias, loop_rel, w_loop);

    dim3 gg(GEMM_MBLK, 2);
    k_gemm_mma<<<gg, 256, SMEM_GEMM>>>(hout);

    k_colstats<<<512, D>>>(hout);
    k_bn_finalize<<<1, D>>>(bn_gamma, bn_beta);
    k_bn_apply<<<(int)(((size_t)NN * D + 255) / 256), 256>>>(hout);

    k_relgemm<<<RR, D>>>(r, w_rel, rout);
}

// round 4
// speedup vs baseline: 1.5256x; 1.0250x over previous
#include <cuda_runtime.h>
#include <cuda_bf16.h>
#include <math.h>
#include <stdint.h>

#define D      256
#define NN     100000
#define EE     1000000
#define HALF_E (EE / 2)
#define RR     474
#define SCAN_BS 1024
#define NB_SCAN ((NN + SCAN_BS - 1) / SCAN_BS)   // 98
#define BN_EPS 1e-5f

#define KTOT   768          // combined K: [pre_in | pre_out | x]
#define NKS    48           // 768 / 16
#define GEMM_MBLK ((NN + 127) / 128)   // 782

// SMEM stage layout: A (2 splits x 128 rows x 48B) | B (2 x 128 x 48B)
#define ROWB    48
#define ASPL    (128 * ROWB)       // 6144
#define AREG    (2 * ASPL)         // 12288
#define STAGE   (2 * AREG)         // 24576
#define NSTAGE  3
#define SM_STATS (NSTAGE * STAGE)          // 73728: float cs[128], css[128]
#define SMEM_GEMM (SM_STATS + 1024)        // 74752

// ---------------- static device scratch ----------------
__device__ __nv_bfloat16 g_Ahi[(size_t)NN * KTOT];
__device__ __nv_bfloat16 g_Amid[(size_t)NN * KTOT];
__device__ __nv_bfloat16 g_Bhi[(size_t)D * KTOT];    // [n][k]
__device__ __nv_bfloat16 g_Bmid[(size_t)D * KTOT];
__device__ int      g_cnt[NN];
__device__ int      g_start[NN];
__device__ int      g_cursor[NN];
__device__ unsigned g_epack[EE];   // mode<<31 | et<<17 | col
__device__ float    g_dinv[NN];
__device__ int      g_bsum[NB_SCAN];
__device__ float    g_bias2[D];
__device__ float    g_colsum[D];
__device__ float    g_colsumsq[D];
__device__ float    g_scale[D];
__device__ float    g_shift[D];

// ---------------- helpers ----------------
__device__ __forceinline__ uint32_t smem_u32(const void* p) {
    uint32_t a;
    asm("{ .reg .u64 t; cvta.to.shared.u64 t, %1; cvt.u32.u64 %0, t; }" : "=r"(a) : "l"(p));
    return a;
}

#define CP_ASYNC16(dst, src, sz) \
    asm volatile("cp.async.cg.shared.global [%0], [%1], 16, %2;" \
        :: "r"(dst), "l"(src), "r"(sz) : "memory")
#define CP_COMMIT() asm volatile("cp.async.commit_group;" ::: "memory")
#define CP_WAIT2()  asm volatile("cp.async.wait_group 2;" ::: "memory")

#define LDMATRIX_X4(r0, r1, r2, r3, addr) \
    asm volatile("ldmatrix.sync.aligned.m8n8.x4.shared.b16 {%0,%1,%2,%3}, [%4];" \
        : "=r"(r0), "=r"(r1), "=r"(r2), "=r"(r3) : "r"(addr))

#define MMA16816(C, A, B0, B1) \
    asm volatile("mma.sync.aligned.m16n8k16.row.col.f32.bf16.bf16.f32 " \
        "{%0,%1,%2,%3}, {%4,%5,%6,%7}, {%8,%9}, {%0,%1,%2,%3};" \
        : "+f"((C)[0]), "+f"((C)[1]), "+f"((C)[2]), "+f"((C)[3]) \
        : "r"((A)[0]), "r"((A)[1]), "r"((A)[2]), "r"((A)[3]), "r"(B0), "r"(B1))

// split fp32 -> bf16 hi + bf16 mid, 8 values, 16B stores
__device__ __forceinline__ void split_store8(__nv_bfloat16* dHi, __nv_bfloat16* dMid,
                                             const float* v) {
    uint32_t h[4], m[4];
#pragma unroll
    for (int q = 0; q < 4; q++) {
        float a = v[2 * q], b = v[2 * q + 1];
        __nv_bfloat16 ha = __float2bfloat16_rn(a), hb = __float2bfloat16_rn(b);
        float ma = a - __bfloat162float(ha), mb = b - __bfloat162float(hb);
        __nv_bfloat162 hp; hp.x = ha; hp.y = hb;
        __nv_bfloat162 mp = __floats2bfloat162_rn(ma, mb);
        h[q] = *reinterpret_cast<uint32_t*>(&hp);
        m[q] = *reinterpret_cast<uint32_t*>(&mp);
    }
    *(uint4*)dHi = make_uint4(h[0], h[1], h[2], h[3]);
    *(uint4*)dMid = make_uint4(m[0], m[1], m[2], m[3]);
}

// ---------------- CSR build ----------------
__global__ void k_zero() {
    int i = blockIdx.x * blockDim.x + threadIdx.x;
    if (i < NN) g_cnt[i] = 0;
    if (i < D) { g_colsum[i] = 0.f; g_colsumsq[i] = 0.f; }
}
__global__ void k_count(const int* __restrict__ rowp) {
    int e = blockIdx.x * blockDim.x + threadIdx.x;
    if (e < EE) atomicAdd(&g_cnt[rowp[e]], 1);
}
// scan + dinv fused
__global__ void k_scan_local() {
    __shared__ int s[SCAN_BS];
    int t = threadIdx.x;
    int i = blockIdx.x * SCAN_BS + t;
    int v = (i < NN) ? g_cnt[i] : 0;
    if (i < NN) g_dinv[i] = (v > 0) ? rsqrtf((float)v) : 0.f;
    s[t] = v;
    __syncthreads();
    for (int off = 1; off < SCAN_BS; off <<= 1) {
        int a = (t >= off) ? s[t - off] : 0;
        __syncthreads();
        s[t] += a;
        __syncthreads();
    }
    if (i < NN) g_start[i] = s[t] - v;
    if (t == SCAN_BS - 1) g_bsum[blockIdx.x] = s[t];
}
__global__ void k_scan_bsum() {
    if (threadIdx.x == 0) {
        int acc = 0;
        for (int b = 0; b < NB_SCAN; b++) { int t = g_bsum[b]; g_bsum[b] = acc; acc += t; }
    }
}
__global__ void k_scan_fixup() {
    int i = blockIdx.x * blockDim.x + threadIdx.x;
    if (i < NN) {
        int s = g_start[i] + g_bsum[i >> 10];
        g_start[i] = s;
        g_cursor[i] = s;
    }
}
// counting-sort fill with packed payload: mode<<31 | et<<17 | col
__global__ void k_fill(const int* __restrict__ rowp,
                       const int* __restrict__ colp,
                       const int* __restrict__ etp) {
    int e = blockIdx.x * blockDim.x + threadIdx.x;
    if (e < EE) {
        int pos = atomicAdd(&g_cursor[rowp[e]], 1);
        unsigned pk = ((e < HALF_E) ? 0u : 0x80000000u) |
                      ((unsigned)etp[e] << 17) | (unsigned)colp[e];
        g_epack[pos] = pk;
    }
}

// ---------------- aggregate (+ own-x split) ----------------
__global__ void k_aggregate(const float* __restrict__ x,
                            const float* __restrict__ r) {
    int node = blockIdx.x * 8 + (threadIdx.x >> 5);
    if (node >= NN) return;
    int lane = threadIdx.x & 31;
    int base = lane * 8;
    size_t rb = (size_t)node * KTOT;

    // own x row -> columns [512, 768)
    {
        const float4* xs = (const float4*)(x + (size_t)node * D + base);
        float4 v0 = xs[0], v1 = xs[1];
        float v[8] = {v0.x, v0.y, v0.z, v0.w, v1.x, v1.y, v1.z, v1.w};
        split_store8(g_Ahi + rb + 512 + base, g_Amid + rb + 512 + base, v);
    }

    float ain[8] = {0}, aout[8] = {0};
    int s = g_start[node];
    int c = g_cnt[node];
    float di = g_dinv[node];
    int end = s + c;

    unsigned pk_next = (c > 0) ? g_epack[s] : 0u;
    for (int p = s; p < end; p++) {
        unsigned pk = pk_next;
        if (p + 1 < end) pk_next = g_epack[p + 1];
        int cl = pk & 0x1FFFF;
        int et = (pk >> 17) & 0x1FF;
        float nrm = di * g_dinv[cl];
        const float4* xp = (const float4*)(x + (size_t)cl * D + base);
        const float4* rp = (const float4*)(r + (size_t)et * D + base);
        float4 xv0 = xp[0], xv1 = xp[1];
        float4 rv0 = rp[0], rv1 = rp[1];
        float d0[8] = {xv0.x - rv0.x, xv0.y - rv0.y, xv0.z - rv0.z, xv0.w - rv0.w,
                       xv1.x - rv1.x, xv1.y - rv1.y, xv1.z - rv1.z, xv1.w - rv1.w};
        if (!(pk & 0x80000000u)) {
#pragma unroll
            for (int j = 0; j < 8; j++) ain[j] += nrm * d0[j];
        } else {
#pragma unroll
            for (int j = 0; j < 8; j++) aout[j] += nrm * d0[j];
        }
    }
    split_store8(g_Ahi + rb + base,       g_Amid + rb + base,       ain);
    split_store8(g_Ahi + rb + 256 + base, g_Amid + rb + 256 + base, aout);
}

// ---------------- combined small kernels: bsplit | bias2 | relgemm ----------------
__global__ void k_misc(const float* __restrict__ w_in,
                       const float* __restrict__ w_out,
                       const float* __restrict__ w_loop,
                       const float* __restrict__ bias,
                       const float* __restrict__ loop_rel,
                       const float* __restrict__ r,
                       const float* __restrict__ w_rel,
                       float* __restrict__ rout) {
    int b = blockIdx.x;
    int n = threadIdx.x;
    if (b < KTOT) {                      // W transpose-split
        int k = b;
        const float* W = (k < 256) ? w_in : (k < 512) ? w_out : w_loop;
        float v = W[(size_t)(k & 255) * D + n];
        __nv_bfloat16 h = __float2bfloat16_rn(v);
        g_Bhi[(size_t)n * KTOT + k] = h;
        g_Bmid[(size_t)n * KTOT + k] = __float2bfloat16_rn(v - __bfloat162float(h));
    } else if (b == KTOT) {              // bias2 = bias - loop_rel @ w_loop
        float acc = bias[n];
        for (int k = 0; k < D; k++)
            acc -= loop_rel[k] * w_loop[k * D + n];
        g_bias2[n] = acc;
    } else {                             // relgemm row
        int row = b - KTOT - 1;
        const float* rr = r + (size_t)row * D;
        float acc = 0.f;
#pragma unroll 8
        for (int k = 0; k < D; k++)
            acc += rr[k] * w_rel[k * D + n];
        rout[(size_t)row * D + n] = acc;
    }
}

// ---------------- mma.sync bf16x3 GEMM + fused column stats ----------------
__device__ __forceinline__ void load_stage(uint32_t sb, int buf, int kOff,
                                           int rowBase, int colBase, int tid) {
    uint32_t base = sb + buf * STAGE;
#pragma unroll
    for (int i = 0; i < 4; i++) {
        int c = tid + i * 256;
        int isB   = c >> 9;
        int split = (c >> 8) & 1;
        int row   = (c >> 1) & 127;
        int half  = c & 1;
        uint32_t dst = base + isB * AREG + split * ASPL + row * ROWB + half * 16;
        const __nv_bfloat16* src;
        int sz = 16;
        if (!isB) {
            int gr = rowBase + row;
            if (gr >= NN) { gr = 0; sz = 0; }
            src = (split ? g_Amid : g_Ahi) + (size_t)gr * KTOT + kOff + half * 8;
        } else {
            int gc = colBase + row;
            src = (split ? g_Bmid : g_Bhi) + (size_t)gc * KTOT + kOff + half * 8;
        }
        CP_ASYNC16(dst, (const void*)src, sz);
    }
}

__global__ void __launch_bounds__(256, 1)
k_gemm_mma(float* __restrict__ hout) {
    extern __shared__ char smem[];
    uint32_t sb = smem_u32(smem);
    int tid = threadIdx.x;
    int lane = tid & 31, wid = tid >> 5;
    int warp_m = wid & 1;        // 2 warps over M=128 (m64 each)
    int warp_n = wid >> 1;       // 4 warps over N=128 (n32 each)
    int colBase = blockIdx.x * 128;   // x = col so paired col-blocks are adjacent bids
    int rowBase = blockIdx.y * 128;

    float c[4][4][4];
#pragma unroll
    for (int i = 0; i < 4; i++)
#pragma unroll
        for (int j = 0; j < 4; j++)
#pragma unroll
            for (int q = 0; q < 4; q++) c[i][j][q] = 0.f;

#pragma unroll
    for (int s = 0; s < NSTAGE; s++) {
        load_stage(sb, s, s * 16, rowBase, colBase, tid);
        CP_COMMIT();
    }

    uint32_t a_off = (lane & 15) * ROWB + (lane >> 4) * 16;
    uint32_t b_off = (((lane >> 4) << 3) + (lane & 7)) * ROWB + ((lane >> 3) & 1) * 16;

    for (int ks = 0; ks < NKS; ks++) {
        CP_WAIT2();
        __syncthreads();
        uint32_t st = sb + (ks % 3) * STAGE;

        uint32_t a[2][4][4];
#pragma unroll
        for (int split = 0; split < 2; split++)
#pragma unroll
            for (int mt = 0; mt < 4; mt++) {
                uint32_t addr = st + split * ASPL +
                                (warp_m * 64 + mt * 16) * ROWB + a_off;
                LDMATRIX_X4(a[split][mt][0], a[split][mt][1],
                            a[split][mt][2], a[split][mt][3], addr);
            }
        uint32_t b[2][2][4];
#pragma unroll
        for (int split = 0; split < 2; split++)
#pragma unroll
            for (int pr = 0; pr < 2; pr++) {
                uint32_t addr = st + AREG + split * ASPL +
                                (warp_n * 32 + pr * 16) * ROWB + b_off;
                LDMATRIX_X4(b[split][pr][0], b[split][pr][1],
                            b[split][pr][2], b[split][pr][3], addr);
            }
#pragma unroll
        for (int mt = 0; mt < 4; mt++)
#pragma unroll
            for (int nt = 0; nt < 4; nt++) {
                int pr = nt >> 1, ix = (nt & 1) * 2;
                MMA16816(c[mt][nt], a[0][mt], b[0][pr][ix], b[0][pr][ix + 1]);
                MMA16816(c[mt][nt], a[0][mt], b[1][pr][ix], b[1][pr][ix + 1]);
                MMA16816(c[mt][nt], a[1][mt], b[0][pr][ix], b[0][pr][ix + 1]);
            }
        __syncthreads();
        if (ks + 3 < NKS)
            load_stage(sb, ks % 3, (ks + 3) * 16, rowBase, colBase, tid);
        CP_COMMIT();
    }

    // ---- epilogue: write hout + per-CTA column stats ----
    float* cs  = (float*)(smem + SM_STATS);        // [128] sum
    float* css = (float*)(smem + SM_STATS) + 128;  // [128] sumsq
    __syncthreads();
    ((float*)(smem + SM_STATS))[tid] = 0.f;        // 256 floats
    __syncthreads();

#pragma unroll
    for (int nt = 0; nt < 4; nt++) {
        int lcol = warp_n * 32 + nt * 8 + (lane & 3) * 2;
        int col = colBase + lcol;
        float b0 = g_bias2[col], b1 = g_bias2[col + 1];
        float s0 = 0.f, s1 = 0.f, q0 = 0.f, q1 = 0.f;
#pragma unroll
        for (int mt = 0; mt < 4; mt++) {
            int row = rowBase + warp_m * 64 + mt * 16 + (lane >> 2);
            if (row < NN) {
                float v0 = c[mt][nt][0] + b0, v1 = c[mt][nt][1] + b1;
                *(float2*)(hout + (size_t)row * D + col) = make_float2(v0, v1);
                s0 += v0; s1 += v1; q0 += v0 * v0; q1 += v1 * v1;
            }
            int row2 = row + 8;
            if (row2 < NN) {
                float v0 = c[mt][nt][2] + b0, v1 = c[mt][nt][3] + b1;
                *(float2*)(hout + (size_t)row2 * D + col) = make_float2(v0, v1);
                s0 += v0; s1 += v1; q0 += v0 * v0; q1 += v1 * v1;
            }
        }
        atomicAdd(&cs[lcol], s0);
        atomicAdd(&cs[lcol + 1], s1);
        atomicAdd(&css[lcol], q0);
        atomicAdd(&css[lcol + 1], q1);
    }
    __syncthreads();
    if (tid < 128) atomicAdd(&g_colsum[colBase + tid], cs[tid]);
    else           atomicAdd(&g_colsumsq[colBase + (tid - 128)], css[tid - 128]);
}

// ---------------- BN finalize / apply ----------------
__global__ void k_bn_finalize(const float* __restrict__ gamma,
                              const float* __restrict__ beta) {
    int c = threadIdx.x;
    float mean = g_colsum[c] / (float)NN;
    float var = g_colsumsq[c] / (float)NN - mean * mean;
    float inv = rsqrtf(var + BN_EPS);
    float sc = gamma[c] * inv;
    g_scale[c] = sc;
    g_shift[c] = beta[c] - mean * sc;
}
__global__ void k_bn_apply(float* __restrict__ hout) {
    size_t i = (size_t)blockIdx.x * blockDim.x + threadIdx.x;
    size_t total = (size_t)NN * D;
    if (i < total) {
        int c = (int)(i & (D - 1));
        hout[i] = tanhf(hout[i] * g_scale[c] + g_shift[c]);
    }
}

// ---------------- launch ----------------
extern "C" void kernel_launch(void* const* d_in, const int* in_sizes, int n_in,
                              void* d_out, int out_size) {
    const float* x        = (const float*)d_in[0];
    const float* r        = (const float*)d_in[1];
    const float* w_in     = (const float*)d_in[2];
    const float* w_out    = (const float*)d_in[3];
    const float* w_loop   = (const float*)d_in[4];
    const float* w_rel    = (const float*)d_in[5];
    const float* loop_rel = (const float*)d_in[6];
    const float* bias     = (const float*)d_in[7];
    const float* bn_gamma = (const float*)d_in[8];
    const float* bn_beta  = (const float*)d_in[9];
    const int*   edge_idx = (const int*)d_in[10];
    const int*   edge_typ = (const int*)d_in[11];

    const int* rowp = edge_idx;
    const int* colp = edge_idx + EE;

    float* hout = (float*)d_out;
    float* rout = (float*)d_out + (size_t)NN * D;

    int gN = (NN + 255) / 256;
    int gE = (EE + 255) / 256;

    cudaFuncSetAttribute(k_gemm_mma, cudaFuncAttributeMaxDynamicSharedMemorySize, SMEM_GEMM);

    k_zero<<<gN, 256>>>();
    k_count<<<gE, 256>>>(rowp);
    k_scan_local<<<NB_SCAN, SCAN_BS>>>();
    k_scan_bsum<<<1, 32>>>();
    k_scan_fixup<<<gN, 256>>>();
    k_fill<<<gE, 256>>>(rowp, colp, edge_typ);
    k_aggregate<<<(NN + 7) / 8, 256>>>(x, r);
    k_misc<<<KTOT + 1 + RR, D>>>(w_in, w_out, w_loop, bias, loop_rel, r, w_rel, rout);

    dim3 gg(2, GEMM_MBLK);
    k_gemm_mma<<<gg, 256, SMEM_GEMM>>>(hout);

    k_bn_finalize<<<1, D>>>(bn_gamma, bn_beta);
    k_bn_apply<<<(int)(((size_t)NN * D + 255) / 256), 256>>>(hout);
}